// round 15
// baseline (speedup 1.0000x reference)
#include <cuda_runtime.h>
#include <cuda_fp16.h>
#include <cstdint>

// ---------------------------------------------------------------------------
// Problem constants
// ---------------------------------------------------------------------------
#define N_NODES   4096
#define M_NEIGH   8192
#define IN_DIM    4096
#define OUT_DIM   1024
#define NUM_SAMPLE 10
#define R_TOTAL   (N_NODES + M_NEIGH)   // 12288

// Scratch (device globals — allocation-free per harness rules)
__device__ __align__(16) __half g_Hh[(size_t)N_NODES * IN_DIM];   // 32 MB aggregated feats fp16
__device__ __align__(16) __half g_Wh[(size_t)OUT_DIM * IN_DIM];   // 8 MB  W fp16
__device__ float g_s[R_TOTAL];                                     // attention pre-scores
__device__ float g_q[2 * IN_DIM];                                  // q1 = W^T a1, q2 = W^T a2
__device__ float g_w[N_NODES * NUM_SAMPLE];                        // softmax weights (0 for dups)
__device__ int   g_id[N_NODES * NUM_SAMPLE];                       // neighbor ids

// ---------------------------------------------------------------------------
// PTX helpers (base ISA only)
// ---------------------------------------------------------------------------
__device__ __forceinline__ uint32_t smem_u32(const void* p) {
    uint32_t a;
    asm("{ .reg .u64 t; cvta.to.shared.u64 t, %1; cvt.u32.u64 %0, t; }" : "=r"(a) : "l"(p));
    return a;
}

__device__ __forceinline__ void cp16(void* dst_smem, const void* src) {
    uint32_t d = smem_u32(dst_smem);
    asm volatile("cp.async.cg.shared.global [%0], [%1], 16;" :: "r"(d), "l"(src) : "memory");
}
#define CP_COMMIT() asm volatile("cp.async.commit_group;" ::: "memory")
#define CP_WAIT1()  asm volatile("cp.async.wait_group 1;" ::: "memory")
#define CP_WAIT0()  asm volatile("cp.async.wait_group 0;" ::: "memory")

#define LDSM4(r0, r1, r2, r3, addr)                                            \
    asm volatile("ldmatrix.sync.aligned.m8n8.x4.shared.b16 {%0,%1,%2,%3}, [%4];" \
                 : "=r"(r0), "=r"(r1), "=r"(r2), "=r"(r3) : "r"(addr))

// f16-accumulate MMA: D(2xb32 = 4 halves) = A*B + D.  rt ~ half of f32-acc.
__device__ __forceinline__ void mma_f16acc(uint32_t* d, const uint32_t* a, const uint32_t* b) {
    asm volatile(
        "mma.sync.aligned.m16n8k16.row.col.f16.f16.f16.f16 "
        "{%0,%1}, {%2,%3,%4,%5}, {%6,%7}, {%0,%1};\n"
        : "+r"(d[0]), "+r"(d[1])
        : "r"(a[0]), "r"(a[1]), "r"(a[2]), "r"(a[3]),
          "r"(b[0]), "r"(b[1]));
}

// ---------------------------------------------------------------------------
// fp32 -> fp16 conversion (W only, one-time pass)
// ---------------------------------------------------------------------------
__global__ void to_half(const float4* __restrict__ src, __half2* __restrict__ dst, int n4)
{
    int i = blockIdx.x * blockDim.x + threadIdx.x;
    if (i < n4) {
        float4 v = src[i];
        dst[2 * i + 0] = __floats2half2_rn(v.x, v.y);
        dst[2 * i + 1] = __floats2half2_rn(v.z, v.w);
    }
}

// ---------------------------------------------------------------------------
// q += W^T a partials.  grid (IN_DIM/128, OUT_DIM/128); g_q pre-zeroed.
// ---------------------------------------------------------------------------
__global__ void compute_q(const float* __restrict__ W, const float* __restrict__ av)
{
    __shared__ float sa[256];
    const int ob = blockIdx.y * 128;
    if (threadIdx.x < 128) sa[threadIdx.x] = av[ob + threadIdx.x];
    else                   sa[threadIdx.x] = av[OUT_DIM + ob + threadIdx.x - 128];
    __syncthreads();

    const int k = blockIdx.x * 128 + (threadIdx.x & 127);
    if (threadIdx.x >= 128) return;

    float a1 = 0.0f, a2 = 0.0f;
#pragma unroll 4
    for (int o = 0; o < 128; o++) {
        const float w = W[(size_t)(ob + o) * IN_DIM + k];
        a1 = fmaf(w, sa[o], a1);
        a2 = fmaf(w, sa[128 + o], a2);
    }
    atomicAdd(&g_q[k], a1);
    atomicAdd(&g_q[IN_DIM + k], a2);
}

// ---------------------------------------------------------------------------
// Pre-scores from RAW features: s[r] = dot(X[r,:], q).  One warp per row.
// ---------------------------------------------------------------------------
__global__ void score_kernel(const float* __restrict__ node, const float* __restrict__ neigh)
{
    const int warp = (blockIdx.x * blockDim.x + threadIdx.x) >> 5;
    const int lane = threadIdx.x & 31;
    if (warp >= R_TOTAL) return;

    const float* x = (warp < N_NODES) ? node  + (size_t)warp * IN_DIM
                                      : neigh + (size_t)(warp - N_NODES) * IN_DIM;
    const float* q = (warp < N_NODES) ? g_q : (g_q + IN_DIM);

    float sum = 0.0f;
#pragma unroll 8
    for (int c = lane * 4; c < IN_DIM; c += 32 * 4) {
        float4 xv = *reinterpret_cast<const float4*>(x + c);
        float4 qv = *reinterpret_cast<const float4*>(q + c);
        sum = fmaf(xv.x, qv.x, sum);
        sum = fmaf(xv.y, qv.y, sum);
        sum = fmaf(xv.z, qv.z, sum);
        sum = fmaf(xv.w, qv.w, sum);
    }
#pragma unroll
    for (int o = 16; o > 0; o >>= 1)
        sum += __shfl_down_sync(0xFFFFFFFFu, sum, o);
    if (lane == 0) g_s[warp] = sum;
}

// ---------------------------------------------------------------------------
// Softmax prep: one thread per node.  All idx + g_s loads prefetched
// (independent, MLP=10) before the dedupe/softmax register pass.
// ---------------------------------------------------------------------------
__global__ void softmax_prep(const int* __restrict__ nbr_idx)
{
    const int i = blockIdx.x * blockDim.x + threadIdx.x;
    if (i >= N_NODES) return;

    int   idxs[NUM_SAMPLE];
    float sval[NUM_SAMPLE];
#pragma unroll
    for (int k = 0; k < NUM_SAMPLE; k++)
        idxs[k] = nbr_idx[i * NUM_SAMPLE + k];
#pragma unroll
    for (int k = 0; k < NUM_SAMPLE; k++)
        sval[k] = g_s[N_NODES + idxs[k]];          // 10 independent L2 loads

    const float s1 = g_s[i];
    int   ids[NUM_SAMPLE];
    float sc[NUM_SAMPLE];
    int n = 0;
    float mx = -1e30f;
#pragma unroll
    for (int k = 0; k < NUM_SAMPLE; k++) {
        int j = idxs[k];
        bool dup = false;
        for (int t = 0; t < n; t++)
            if (ids[t] == j) { dup = true; break; }
        if (dup) continue;
        float x  = s1 + sval[k];
        float sv = (x >= 0.0f) ? x : 0.2f * x;     // leaky_relu slope 0.2
        ids[n] = j;
        sc[n]  = sv;
        mx = fmaxf(mx, sv);
        n++;
    }
    float denom = 0.0f;
    for (int t = 0; t < n; t++) {
        float e = __expf(sc[t] - mx);
        sc[t] = e;
        denom += e;
    }
    const float inv = 1.0f / denom;
#pragma unroll
    for (int t = 0; t < NUM_SAMPLE; t++) {
        g_w[i * NUM_SAMPLE + t]  = (t < n) ? sc[t] * inv : 0.0f;
        g_id[i * NUM_SAMPLE + t] = (t < n) ? ids[t] : 0;
    }
}

// ---------------------------------------------------------------------------
// Attention gather, column-tiled for L2 residency (4 chunks x 1024 cols).
// ---------------------------------------------------------------------------
__global__ __launch_bounds__(256)
void agg_gather(const float* __restrict__ neigh)
{
    const int i = blockIdx.x;

    __shared__ float s_w[NUM_SAMPLE];
    __shared__ int   s_idx[NUM_SAMPLE];
    if (threadIdx.x < NUM_SAMPLE) {
        s_w[threadIdx.x]   = g_w[i * NUM_SAMPLE + threadIdx.x];
        s_idx[threadIdx.x] = g_id[i * NUM_SAMPLE + threadIdx.x];
    }
    __syncthreads();

    const int c0 = blockIdx.y * (IN_DIM / 4) + threadIdx.x * 4;
    float4 acc = make_float4(0.f, 0.f, 0.f, 0.f);
#pragma unroll
    for (int t = 0; t < NUM_SAMPLE; t++) {
        const float ww = s_w[t];
        const float4 v = *reinterpret_cast<const float4*>(
            neigh + (size_t)s_idx[t] * IN_DIM + c0);
        acc.x = fmaf(ww, v.x, acc.x);
        acc.y = fmaf(ww, v.y, acc.y);
        acc.z = fmaf(ww, v.z, acc.z);
        acc.w = fmaf(ww, v.w, acc.w);
    }

    __half2 h[2];
    h[0] = __floats2half2_rn(acc.x, acc.y);
    h[1] = __floats2half2_rn(acc.z, acc.w);
    *reinterpret_cast<uint2*>(g_Hh + (size_t)i * IN_DIM + c0)
        = *reinterpret_cast<uint2*>(h);
}

// ---------------------------------------------------------------------------
// fp16 mma.sync GEMM with f16 accumulate + per-chunk fp32 promotion:
//   out[r, o] = sum_k H_h[r, k] * W_h[o, k]
// CTA tile 128x128, BK=64, 2-stage cp.async pipe, 16 warps (32x32 each),
// 512 threads, 1 CTA/SM.  ldmatrix fragment loads.
// ---------------------------------------------------------------------------
#define BKH       64                     // halves per K-chunk
#define NCHUNK    (IN_DIM / BKH)         // 64
#define STRH      72                     // halves per smem row (64 + 8 pad)
#define TILE_H    (128 * STRH)           // 9216 halves per tile
#define STAGE_H   (2 * TILE_H)           // A + B
#define SMEM_GEMM (2 * STAGE_H * 2)      // 73728 bytes (2 stages)

__global__ __launch_bounds__(512, 1)
void gemm_mma(float* __restrict__ out)
{
    extern __shared__ __half sm[];
    const uint32_t smb = smem_u32(sm);

    const int tid    = threadIdx.x;
    const int wid    = tid >> 5;         // 0..15
    const int lane   = tid & 31;
    const int g      = lane >> 2;
    const int c4     = lane & 3;
    const int l8     = lane & 7;
    const int warp_m = (wid & 3) * 32;   // 4 warp-rows
    const int warp_n = (wid >> 2) * 32;  // 4 warp-cols

    const int row0 = blockIdx.y * 128;
    const int col0 = blockIdx.x * 128;

    const __half* X  = g_Hh + (size_t)row0 * IN_DIM;
    const __half* Wb = g_Wh + (size_t)col0 * IN_DIM;

    // ldmatrix per-lane source offsets (halves within tile)
    const uint32_t a_half = (uint32_t)(warp_m + l8 + (lane & 8)) * STRH
                          + ((lane & 16) ? 8u : 0u);
    const uint32_t b_half = (uint32_t)(warp_n + l8 + ((lane & 16) ? 8 : 0)) * STRH
                          + ((lane & 8) ? 8u : 0u);

    float    c[2][4][4];                 // fp32 running accumulators
    uint32_t d[2][4][2];                 // f16 chunk accumulators
#pragma unroll
    for (int mt = 0; mt < 2; mt++)
#pragma unroll
        for (int j = 0; j < 4; j++) {
#pragma unroll
            for (int q = 0; q < 4; q++) c[mt][j][q] = 0.0f;
            d[mt][j][0] = 0u; d[mt][j][1] = 0u;
        }

#define ISSUE(ch) do {                                                         \
        __half* As_ = sm + ((ch) & 1) * STAGE_H;                               \
        __half* Bs_ = As_ + TILE_H;                                            \
        _Pragma("unroll")                                                      \
        for (int l = 0; l < 2; l++) {                                          \
            int i = tid + l * 512;            /* 0..1023 */                    \
            int r = i >> 3, s = i & 7;                                         \
            cp16(As_ + r * STRH + s * 8,                                       \
                 X  + (size_t)r * IN_DIM + (ch) * BKH + s * 8);                \
            cp16(Bs_ + r * STRH + s * 8,                                       \
                 Wb + (size_t)r * IN_DIM + (ch) * BKH + s * 8);                \
        }                                                                      \
        CP_COMMIT();                                                           \
    } while (0)

    ISSUE(0);

    for (int ch = 0; ch < NCHUNK; ch++) {
        if (ch + 1 < NCHUNK) { ISSUE(ch + 1); CP_WAIT1(); }
        else                 { CP_WAIT0(); }
        __syncthreads();

        const uint32_t stageA = smb + (uint32_t)((ch & 1) * STAGE_H) * 2u;
        const uint32_t stageB = stageA + TILE_H * 2u;
        const uint32_t aAddr  = stageA + a_half * 2u;
        const uint32_t bAddr  = stageB + b_half * 2u;

#pragma unroll
        for (int ks = 0; ks < 4; ks++) {          // 4 K-steps of 16 halves
            const uint32_t ko = (uint32_t)(ks * 16) * 2u;
            uint32_t a[2][4], b[4][2];
#pragma unroll
            for (int mt = 0; mt < 2; mt++)
                LDSM4(a[mt][0], a[mt][1], a[mt][2], a[mt][3],
                      aAddr + (uint32_t)(mt * 16 * STRH) * 2u + ko);
            LDSM4(b[0][0], b[0][1], b[1][0], b[1][1], bAddr + ko);
            LDSM4(b[2][0], b[2][1], b[3][0], b[3][1],
                  bAddr + (uint32_t)(16 * STRH) * 2u + ko);
#pragma unroll
            for (int mt = 0; mt < 2; mt++)
#pragma unroll
                for (int j = 0; j < 4; j++)
                    mma_f16acc(d[mt][j], a[mt], b[j]);
        }

        // promote f16 chunk sums into fp32, reset chunk accumulators
#pragma unroll
        for (int mt = 0; mt < 2; mt++)
#pragma unroll
            for (int j = 0; j < 4; j++) {
                float2 f0 = __half22float2(*reinterpret_cast<__half2*>(&d[mt][j][0]));
                float2 f1 = __half22float2(*reinterpret_cast<__half2*>(&d[mt][j][1]));
                c[mt][j][0] += f0.x; c[mt][j][1] += f0.y;
                c[mt][j][2] += f1.x; c[mt][j][3] += f1.y;
                d[mt][j][0] = 0u; d[mt][j][1] = 0u;
            }
        __syncthreads();
    }

    // epilogue: C -> out (fp32, direct)
    float* base = out + (size_t)row0 * OUT_DIM + col0;
#pragma unroll
    for (int mt = 0; mt < 2; mt++) {
        const int r = warp_m + mt * 16 + g;
#pragma unroll
        for (int j = 0; j < 4; j++) {
            const int cc = warp_n + j * 8 + c4 * 2;
            *reinterpret_cast<float2*>(base + (size_t)r * OUT_DIM + cc)
                = make_float2(c[mt][j][0], c[mt][j][1]);
            *reinterpret_cast<float2*>(base + (size_t)(r + 8) * OUT_DIM + cc)
                = make_float2(c[mt][j][2], c[mt][j][3]);
        }
    }
#undef ISSUE
}

// ---------------------------------------------------------------------------
// Launch
// ---------------------------------------------------------------------------
extern "C" void kernel_launch(void* const* d_in, const int* in_sizes, int n_in,
                              void* d_out, int out_size)
{
    const float* node  = (const float*)d_in[0];
    const float* neigh = (const float*)d_in[1];
    const float* W     = (const float*)d_in[2];
    const float* av    = (const float*)d_in[3];
    const int*   idx   = (const int*)d_in[4];
    float*       out   = (float*)d_out;

    cudaFuncSetAttribute(gemm_mma, cudaFuncAttributeMaxDynamicSharedMemorySize, SMEM_GEMM);

    __half2* wh; cudaGetSymbolAddress((void**)&wh, g_Wh);
    float*   qp; cudaGetSymbolAddress((void**)&qp, g_q);

    // 0) W fp32 -> fp16 (8 MB)
    const int nw4 = OUT_DIM * IN_DIM / 4;
    to_half<<<(nw4 + 255) / 256, 256>>>((const float4*)W, wh, nw4);

    // 1) exact fp32 score path: q = W^T a (o-parallel partials), s = X @ q
    cudaMemsetAsync(qp, 0, 2 * IN_DIM * sizeof(float));
    compute_q<<<dim3(IN_DIM / 128, OUT_DIM / 128), 256>>>(W, av);
    score_kernel<<<(R_TOTAL * 32) / 256, 256>>>(node, neigh);

    // 2) softmax weights (dedupe + leaky_relu + softmax), one thread per node
    softmax_prep<<<N_NODES / 128, 128>>>(idx);

    // 3) H = attn @ neigh, column-tiled (4 chunks x 1024 cols, L2-resident)
    agg_gather<<<dim3(N_NODES, 4), 256>>>(neigh);

    // 4) out = H @ W^T  (fp16 mma.sync, f16 acc + fp32 promotion)
    gemm_mma<<<dim3(OUT_DIM / 128, N_NODES / 128), 512, SMEM_GEMM>>>(out);
}

// round 17
// speedup vs baseline: 1.0023x; 1.0023x over previous
#include <cuda_runtime.h>
#include <cuda_fp16.h>
#include <cstdint>

// ---------------------------------------------------------------------------
// Problem constants
// ---------------------------------------------------------------------------
#define N_NODES   4096
#define M_NEIGH   8192
#define IN_DIM    4096
#define OUT_DIM   1024
#define NUM_SAMPLE 10
#define R_TOTAL   (N_NODES + M_NEIGH)   // 12288

// Scratch (device globals — allocation-free per harness rules)
__device__ __align__(16) __half g_Hh[(size_t)N_NODES * IN_DIM];   // 32 MB aggregated feats fp16
__device__ __align__(16) __half g_Wh[(size_t)OUT_DIM * IN_DIM];   // 8 MB  W fp16
__device__ float g_s[R_TOTAL];                                     // attention pre-scores
__device__ float g_q[2 * IN_DIM];                                  // q1 = W^T a1, q2 = W^T a2
__device__ float g_w[N_NODES * NUM_SAMPLE];                        // softmax weights (0 for dups)
__device__ int   g_id[N_NODES * NUM_SAMPLE];                       // neighbor ids

// ---------------------------------------------------------------------------
// PTX helpers (base ISA only)
// ---------------------------------------------------------------------------
__device__ __forceinline__ uint32_t smem_u32(const void* p) {
    uint32_t a;
    asm("{ .reg .u64 t; cvta.to.shared.u64 t, %1; cvt.u32.u64 %0, t; }" : "=r"(a) : "l"(p));
    return a;
}

__device__ __forceinline__ void cp16(void* dst_smem, const void* src) {
    uint32_t d = smem_u32(dst_smem);
    asm volatile("cp.async.cg.shared.global [%0], [%1], 16;" :: "r"(d), "l"(src) : "memory");
}
#define CP_COMMIT() asm volatile("cp.async.commit_group;" ::: "memory")
#define CP_WAIT1()  asm volatile("cp.async.wait_group 1;" ::: "memory")
#define CP_WAIT0()  asm volatile("cp.async.wait_group 0;" ::: "memory")

#define LDSM4(r0, r1, r2, r3, addr)                                            \
    asm volatile("ldmatrix.sync.aligned.m8n8.x4.shared.b16 {%0,%1,%2,%3}, [%4];" \
                 : "=r"(r0), "=r"(r1), "=r"(r2), "=r"(r3) : "r"(addr))

// f16-accumulate MMA: D(2xb32 = 4 halves) = A*B + D.  rt ~ half of f32-acc.
__device__ __forceinline__ void mma_f16acc(uint32_t* d, const uint32_t* a, const uint32_t* b) {
    asm volatile(
        "mma.sync.aligned.m16n8k16.row.col.f16.f16.f16.f16 "
        "{%0,%1}, {%2,%3,%4,%5}, {%6,%7}, {%0,%1};\n"
        : "+r"(d[0]), "+r"(d[1])
        : "r"(a[0]), "r"(a[1]), "r"(a[2]), "r"(a[3]),
          "r"(b[0]), "r"(b[1]));
}

// ---------------------------------------------------------------------------
// fp32 -> fp16 conversion (W only, one-time pass)
// ---------------------------------------------------------------------------
__global__ void to_half(const float4* __restrict__ src, __half2* __restrict__ dst, int n4)
{
    int i = blockIdx.x * blockDim.x + threadIdx.x;
    if (i < n4) {
        float4 v = src[i];
        dst[2 * i + 0] = __floats2half2_rn(v.x, v.y);
        dst[2 * i + 1] = __floats2half2_rn(v.z, v.w);
    }
}

// ---------------------------------------------------------------------------
// q += W^T a partials.  grid (IN_DIM/128, OUT_DIM/128); g_q pre-zeroed.
// ---------------------------------------------------------------------------
__global__ void compute_q(const float* __restrict__ W, const float* __restrict__ av)
{
    __shared__ float sa[256];
    const int ob = blockIdx.y * 128;
    if (threadIdx.x < 128) sa[threadIdx.x] = av[ob + threadIdx.x];
    else                   sa[threadIdx.x] = av[OUT_DIM + ob + threadIdx.x - 128];
    __syncthreads();

    const int k = blockIdx.x * 128 + (threadIdx.x & 127);
    if (threadIdx.x >= 128) return;

    float a1 = 0.0f, a2 = 0.0f;
#pragma unroll 4
    for (int o = 0; o < 128; o++) {
        const float w = W[(size_t)(ob + o) * IN_DIM + k];
        a1 = fmaf(w, sa[o], a1);
        a2 = fmaf(w, sa[128 + o], a2);
    }
    atomicAdd(&g_q[k], a1);
    atomicAdd(&g_q[IN_DIM + k], a2);
}

// ---------------------------------------------------------------------------
// Pre-scores from RAW features: s[r] = dot(X[r,:], q).  One warp per row.
// ---------------------------------------------------------------------------
__global__ void score_kernel(const float* __restrict__ node, const float* __restrict__ neigh)
{
    const int warp = (blockIdx.x * blockDim.x + threadIdx.x) >> 5;
    const int lane = threadIdx.x & 31;
    if (warp >= R_TOTAL) return;

    const float* x = (warp < N_NODES) ? node  + (size_t)warp * IN_DIM
                                      : neigh + (size_t)(warp - N_NODES) * IN_DIM;
    const float* q = (warp < N_NODES) ? g_q : (g_q + IN_DIM);

    float sum = 0.0f;
#pragma unroll 8
    for (int c = lane * 4; c < IN_DIM; c += 32 * 4) {
        float4 xv = *reinterpret_cast<const float4*>(x + c);
        float4 qv = *reinterpret_cast<const float4*>(q + c);
        sum = fmaf(xv.x, qv.x, sum);
        sum = fmaf(xv.y, qv.y, sum);
        sum = fmaf(xv.z, qv.z, sum);
        sum = fmaf(xv.w, qv.w, sum);
    }
#pragma unroll
    for (int o = 16; o > 0; o >>= 1)
        sum += __shfl_down_sync(0xFFFFFFFFu, sum, o);
    if (lane == 0) g_s[warp] = sum;
}

// ---------------------------------------------------------------------------
// Softmax prep: one thread per node.  All idx + g_s loads prefetched
// (independent, MLP=10) before the dedupe/softmax register pass.
// ---------------------------------------------------------------------------
__global__ void softmax_prep(const int* __restrict__ nbr_idx)
{
    const int i = blockIdx.x * blockDim.x + threadIdx.x;
    if (i >= N_NODES) return;

    int   idxs[NUM_SAMPLE];
    float sval[NUM_SAMPLE];
#pragma unroll
    for (int k = 0; k < NUM_SAMPLE; k++)
        idxs[k] = nbr_idx[i * NUM_SAMPLE + k];
#pragma unroll
    for (int k = 0; k < NUM_SAMPLE; k++)
        sval[k] = g_s[N_NODES + idxs[k]];          // 10 independent L2 loads

    const float s1 = g_s[i];
    int   ids[NUM_SAMPLE];
    float sc[NUM_SAMPLE];
    int n = 0;
    float mx = -1e30f;
#pragma unroll
    for (int k = 0; k < NUM_SAMPLE; k++) {
        int j = idxs[k];
        bool dup = false;
        for (int t = 0; t < n; t++)
            if (ids[t] == j) { dup = true; break; }
        if (dup) continue;
        float x  = s1 + sval[k];
        float sv = (x >= 0.0f) ? x : 0.2f * x;     // leaky_relu slope 0.2
        ids[n] = j;
        sc[n]  = sv;
        mx = fmaxf(mx, sv);
        n++;
    }
    float denom = 0.0f;
    for (int t = 0; t < n; t++) {
        float e = __expf(sc[t] - mx);
        sc[t] = e;
        denom += e;
    }
    const float inv = 1.0f / denom;
#pragma unroll
    for (int t = 0; t < NUM_SAMPLE; t++) {
        g_w[i * NUM_SAMPLE + t]  = (t < n) ? sc[t] * inv : 0.0f;
        g_id[i * NUM_SAMPLE + t] = (t < n) ? ids[t] : 0;
    }
}

// ---------------------------------------------------------------------------
// Attention gather, column-tiled for L2 residency (4 chunks x 1024 cols).
// ---------------------------------------------------------------------------
__global__ __launch_bounds__(256)
void agg_gather(const float* __restrict__ neigh)
{
    const int i = blockIdx.x;

    __shared__ float s_w[NUM_SAMPLE];
    __shared__ int   s_idx[NUM_SAMPLE];
    if (threadIdx.x < NUM_SAMPLE) {
        s_w[threadIdx.x]   = g_w[i * NUM_SAMPLE + threadIdx.x];
        s_idx[threadIdx.x] = g_id[i * NUM_SAMPLE + threadIdx.x];
    }
    __syncthreads();

    const int c0 = blockIdx.y * (IN_DIM / 4) + threadIdx.x * 4;
    float4 acc = make_float4(0.f, 0.f, 0.f, 0.f);
#pragma unroll
    for (int t = 0; t < NUM_SAMPLE; t++) {
        const float ww = s_w[t];
        const float4 v = *reinterpret_cast<const float4*>(
            neigh + (size_t)s_idx[t] * IN_DIM + c0);
        acc.x = fmaf(ww, v.x, acc.x);
        acc.y = fmaf(ww, v.y, acc.y);
        acc.z = fmaf(ww, v.z, acc.z);
        acc.w = fmaf(ww, v.w, acc.w);
    }

    __half2 h[2];
    h[0] = __floats2half2_rn(acc.x, acc.y);
    h[1] = __floats2half2_rn(acc.z, acc.w);
    *reinterpret_cast<uint2*>(g_Hh + (size_t)i * IN_DIM + c0)
        = *reinterpret_cast<uint2*>(h);
}

// ---------------------------------------------------------------------------
// fp16 mma.sync GEMM with f16 accumulate + per-chunk fp32 promotion:
//   out[r, o] = sum_k H_h[r, k] * W_h[o, k]
// CTA tile 128x128, BK=64, 2-stage cp.async pipe, 16 warps (32x32 each),
// 512 threads, 1 CTA/SM.  ldmatrix fragment loads.
// ---------------------------------------------------------------------------
#define BKH       64                     // halves per K-chunk
#define NCHUNK    (IN_DIM / BKH)         // 64
#define STRH      72                     // halves per smem row (64 + 8 pad)
#define TILE_H    (128 * STRH)           // 9216 halves per tile
#define STAGE_H   (2 * TILE_H)           // A + B
#define SMEM_GEMM (2 * STAGE_H * 2)      // 73728 bytes (2 stages)

__global__ __launch_bounds__(512, 1)
void gemm_mma(float* __restrict__ out)
{
    extern __shared__ __half sm[];
    const uint32_t smb = smem_u32(sm);

    const int tid    = threadIdx.x;
    const int wid    = tid >> 5;         // 0..15
    const int lane   = tid & 31;
    const int g      = lane >> 2;
    const int c4     = lane & 3;
    const int l8     = lane & 7;
    const int warp_m = (wid & 3) * 32;   // 4 warp-rows
    const int warp_n = (wid >> 2) * 32;  // 4 warp-cols

    const int row0 = blockIdx.y * 128;
    const int col0 = blockIdx.x * 128;

    const __half* X  = g_Hh + (size_t)row0 * IN_DIM;
    const __half* Wb = g_Wh + (size_t)col0 * IN_DIM;

    // ldmatrix per-lane source offsets (halves within tile)
    const uint32_t a_half = (uint32_t)(warp_m + l8 + (lane & 8)) * STRH
                          + ((lane & 16) ? 8u : 0u);
    const uint32_t b_half = (uint32_t)(warp_n + l8 + ((lane & 16) ? 8 : 0)) * STRH
                          + ((lane & 8) ? 8u : 0u);

    float    c[2][4][4];                 // fp32 running accumulators
    uint32_t d[2][4][2];                 // f16 chunk accumulators
#pragma unroll
    for (int mt = 0; mt < 2; mt++)
#pragma unroll
        for (int j = 0; j < 4; j++) {
#pragma unroll
            for (int q = 0; q < 4; q++) c[mt][j][q] = 0.0f;
            d[mt][j][0] = 0u; d[mt][j][1] = 0u;
        }

#define ISSUE(ch) do {                                                         \
        __half* As_ = sm + ((ch) & 1) * STAGE_H;                               \
        __half* Bs_ = As_ + TILE_H;                                            \
        _Pragma("unroll")                                                      \
        for (int l = 0; l < 2; l++) {                                          \
            int i = tid + l * 512;            /* 0..1023 */                    \
            int r = i >> 3, s = i & 7;                                         \
            cp16(As_ + r * STRH + s * 8,                                       \
                 X  + (size_t)r * IN_DIM + (ch) * BKH + s * 8);                \
            cp16(Bs_ + r * STRH + s * 8,                                       \
                 Wb + (size_t)r * IN_DIM + (ch) * BKH + s * 8);                \
        }                                                                      \
        CP_COMMIT();                                                           \
    } while (0)

    ISSUE(0);

    for (int ch = 0; ch < NCHUNK; ch++) {
        if (ch + 1 < NCHUNK) { ISSUE(ch + 1); CP_WAIT1(); }
        else                 { CP_WAIT0(); }
        __syncthreads();

        const uint32_t stageA = smb + (uint32_t)((ch & 1) * STAGE_H) * 2u;
        const uint32_t stageB = stageA + TILE_H * 2u;
        const uint32_t aAddr  = stageA + a_half * 2u;
        const uint32_t bAddr  = stageB + b_half * 2u;

#pragma unroll
        for (int ks = 0; ks < 4; ks++) {          // 4 K-steps of 16 halves
            const uint32_t ko = (uint32_t)(ks * 16) * 2u;
            uint32_t a[2][4], b[4][2];
#pragma unroll
            for (int mt = 0; mt < 2; mt++)
                LDSM4(a[mt][0], a[mt][1], a[mt][2], a[mt][3],
                      aAddr + (uint32_t)(mt * 16 * STRH) * 2u + ko);
            LDSM4(b[0][0], b[0][1], b[1][0], b[1][1], bAddr + ko);
            LDSM4(b[2][0], b[2][1], b[3][0], b[3][1],
                  bAddr + (uint32_t)(16 * STRH) * 2u + ko);
#pragma unroll
            for (int mt = 0; mt < 2; mt++)
#pragma unroll
                for (int j = 0; j < 4; j++)
                    mma_f16acc(d[mt][j], a[mt], b[j]);
        }

        // promote f16 chunk sums into fp32, reset chunk accumulators
#pragma unroll
        for (int mt = 0; mt < 2; mt++)
#pragma unroll
            for (int j = 0; j < 4; j++) {
                float2 f0 = __half22float2(*reinterpret_cast<__half2*>(&d[mt][j][0]));
                float2 f1 = __half22float2(*reinterpret_cast<__half2*>(&d[mt][j][1]));
                c[mt][j][0] += f0.x; c[mt][j][1] += f0.y;
                c[mt][j][2] += f1.x; c[mt][j][3] += f1.y;
                d[mt][j][0] = 0u; d[mt][j][1] = 0u;
            }
        __syncthreads();
    }

    // epilogue: C -> out (fp32, direct)
    float* base = out + (size_t)row0 * OUT_DIM + col0;
#pragma unroll
    for (int mt = 0; mt < 2; mt++) {
        const int r = warp_m + mt * 16 + g;
#pragma unroll
        for (int j = 0; j < 4; j++) {
            const int cc = warp_n + j * 8 + c4 * 2;
            *reinterpret_cast<float2*>(base + (size_t)r * OUT_DIM + cc)
                = make_float2(c[mt][j][0], c[mt][j][1]);
            *reinterpret_cast<float2*>(base + (size_t)(r + 8) * OUT_DIM + cc)
                = make_float2(c[mt][j][2], c[mt][j][3]);
        }
    }
#undef ISSUE
}

// ---------------------------------------------------------------------------
// Launch
// ---------------------------------------------------------------------------
extern "C" void kernel_launch(void* const* d_in, const int* in_sizes, int n_in,
                              void* d_out, int out_size)
{
    const float* node  = (const float*)d_in[0];
    const float* neigh = (const float*)d_in[1];
    const float* W     = (const float*)d_in[2];
    const float* av    = (const float*)d_in[3];
    const int*   idx   = (const int*)d_in[4];
    float*       out   = (float*)d_out;

    cudaFuncSetAttribute(gemm_mma, cudaFuncAttributeMaxDynamicSharedMemorySize, SMEM_GEMM);

    __half2* wh; cudaGetSymbolAddress((void**)&wh, g_Wh);
    float*   qp; cudaGetSymbolAddress((void**)&qp, g_q);

    // 0) W fp32 -> fp16 (8 MB)
    const int nw4 = OUT_DIM * IN_DIM / 4;
    to_half<<<(nw4 + 255) / 256, 256>>>((const float4*)W, wh, nw4);

    // 1) exact fp32 score path: q = W^T a (o-parallel partials), s = X @ q
    cudaMemsetAsync(qp, 0, 2 * IN_DIM * sizeof(float));
    compute_q<<<dim3(IN_DIM / 128, OUT_DIM / 128), 256>>>(W, av);
    score_kernel<<<(R_TOTAL * 32) / 256, 256>>>(node, neigh);

    // 2) softmax weights (dedupe + leaky_relu + softmax), one thread per node
    softmax_prep<<<N_NODES / 128, 128>>>(idx);

    // 3) H = attn @ neigh, column-tiled (4 chunks x 1024 cols, L2-resident)
    agg_gather<<<dim3(N_NODES, 4), 256>>>(neigh);

    // 4) out = H @ W^T  (fp16 mma.sync, f16 acc + fp32 promotion)
    gemm_mma<<<dim3(OUT_DIM / 128, N_NODES / 128), 512, SMEM_GEMM>>>(out);
}